// round 7
// baseline (speedup 1.0000x reference)
#include <cuda_runtime.h>
#include <mma.h>
#include <math.h>
#include <cstdint>

using namespace nvcuda;

// Problem constants (fixed by the dataset)
#define N_NODES 50000
#define DIM     128
#define N_EDGES 640000

// GEMM tiling: block computes 64 rows x 128 cols with tf32 wmma
#define TM 64
#define LDS_PAD 136                       // padded leading dim (mult of 8)
#define GEMM_SMEM ((DIM*LDS_PAD + TM*LDS_PAD) * 4)   // sW 69632 + sA 34816 = 104448 B

// SpMM staging: warp stages up to STAGE edge-rows (512B each) via cp.async
#define STAGE 16
#define SPMM_SMEM (8 * STAGE * 512)       // 8 warps/block * 8KB = 64KB

// ---------------- scratch (device globals; no allocation allowed) ----------------
__device__ float g_hW[N_NODES*DIM];
__device__ float g_y1[N_NODES*DIM];
__device__ float g_z [N_NODES*DIM];
__device__ float g_y2[N_NODES*DIM];
__device__ int   g_rowptr[N_NODES+1];
__device__ float g_s1[DIM], g_t1[DIM], g_s2[DIM], g_t2[DIM];

__device__ __forceinline__ void cp_async16(uint32_t smem_addr, const void* gptr) {
    asm volatile("cp.async.cg.shared.global [%0], [%1], 16;\n"
                 :: "r"(smem_addr), "l"(gptr) : "memory");
}
__device__ __forceinline__ void cp_async_commit() {
    asm volatile("cp.async.commit_group;\n" ::: "memory");
}
__device__ __forceinline__ void cp_async_wait_all() {
    asm volatile("cp.async.wait_group 0;\n" ::: "memory");
}

// -------- fused: BN folding (block 0) + rowptr build (all blocks) ---------------
__global__ void prep_all(const float* __restrict__ g1, const float* __restrict__ b1,
                         const float* __restrict__ m1, const float* __restrict__ v1,
                         const float* __restrict__ g2, const float* __restrict__ b2,
                         const float* __restrict__ m2, const float* __restrict__ v2,
                         const int* __restrict__ rows, int n, int e)
{
    if (blockIdx.x == 0 && threadIdx.x < DIM) {
        int d = threadIdx.x;
        float s1 = g1[d] * rsqrtf(v1[d] + 1e-3f);
        g_s1[d] = s1; g_t1[d] = b1[d] - m1[d] * s1;
        float s2 = g2[d] * rsqrtf(v2[d] + 1e-3f);
        g_s2[d] = s2; g_t2[d] = b2[d] - m2[d] * s2;
    }
    int r = blockIdx.x * blockDim.x + threadIdx.x;
    if (r > n) return;
    int lo = 0, hi = e;
    while (lo < hi) {
        int mid = (lo + hi) >> 1;
        if (rows[mid] < r) lo = mid + 1; else hi = mid;
    }
    g_rowptr[r] = lo;
}

// ---------------- C[n,128] = (optional BN(A)) @ W (+ optional bias), tf32 wmma --
__global__ void __launch_bounds__(256, 2)
gemm128_tf32(const float* __restrict__ A, const float* __restrict__ W,
             float* __restrict__ C,
             const float* __restrict__ bn_s, const float* __restrict__ bn_t,
             const float* __restrict__ bias, int n)
{
    extern __shared__ float sh[];
    float* sW = sh;                       // [128][136]
    float* sA = sh + DIM * LDS_PAD;       // [64][136]  (reused as epilogue buf)

    const int tid = threadIdx.x;
    const int r0  = blockIdx.x * TM;

    const float4* W4 = (const float4*)W;
    #pragma unroll
    for (int k = 0; k < 16; k++) {
        int idx = tid + k * 256;          // float4 index over 128x128
        float4 w = W4[idx];
        w.x = wmma::__float_to_tf32(w.x);
        w.y = wmma::__float_to_tf32(w.y);
        w.z = wmma::__float_to_tf32(w.z);
        w.w = wmma::__float_to_tf32(w.w);
        int row = idx >> 5, c4 = idx & 31;
        *(float4*)&sW[row * LDS_PAD + c4 * 4] = w;
    }
    #pragma unroll
    for (int k = 0; k < 8; k++) {
        int idx = tid + k * 256;
        int row = idx >> 5, c4 = idx & 31;
        int gr = r0 + row;
        float4 a = make_float4(0.f, 0.f, 0.f, 0.f);
        if (gr < n) {
            a = ((const float4*)A)[gr * 32 + c4];
            if (bn_s) {
                int d = c4 * 4;
                a.x = a.x * bn_s[d + 0] + bn_t[d + 0];
                a.y = a.y * bn_s[d + 1] + bn_t[d + 1];
                a.z = a.z * bn_s[d + 2] + bn_t[d + 2];
                a.w = a.w * bn_s[d + 3] + bn_t[d + 3];
            }
            a.x = wmma::__float_to_tf32(a.x);
            a.y = wmma::__float_to_tf32(a.y);
            a.z = wmma::__float_to_tf32(a.z);
            a.w = wmma::__float_to_tf32(a.w);
        }
        *(float4*)&sA[row * LDS_PAD + c4 * 4] = a;
    }
    __syncthreads();

    const int wid = tid >> 5;
    const int wr  = wid >> 1;            // 0..3 : 16-row group
    const int wc  = wid & 1;             // 0..1 : 64-col group

    wmma::fragment<wmma::accumulator, 16, 16, 8, float> acc[4];
    #pragma unroll
    for (int j = 0; j < 4; j++) wmma::fill_fragment(acc[j], 0.f);

    #pragma unroll
    for (int kk = 0; kk < DIM; kk += 8) {
        wmma::fragment<wmma::matrix_a, 16, 16, 8, wmma::precision::tf32, wmma::row_major> af;
        wmma::load_matrix_sync(af, &sA[(wr * 16) * LDS_PAD + kk], LDS_PAD);
        #pragma unroll
        for (int j = 0; j < 4; j++) {
            wmma::fragment<wmma::matrix_b, 16, 16, 8, wmma::precision::tf32, wmma::row_major> bf;
            wmma::load_matrix_sync(bf, &sW[kk * LDS_PAD + wc * 64 + j * 16], LDS_PAD);
            wmma::mma_sync(acc[j], af, bf, acc[j]);
        }
    }

    __syncthreads();   // everyone done reading sA
    #pragma unroll
    for (int j = 0; j < 4; j++)
        wmma::store_matrix_sync(&sA[(wr * 16) * LDS_PAD + wc * 64 + j * 16],
                                acc[j], LDS_PAD, wmma::mem_row_major);
    __syncthreads();

    #pragma unroll
    for (int k = 0; k < 8; k++) {
        int idx = tid + k * 256;          // 2048 float4 over 64x128
        int row = idx >> 5, c4 = idx & 31;
        int gr = r0 + row;
        if (gr >= n) continue;
        float4 v = *(float4*)&sA[row * LDS_PAD + c4 * 4];
        if (bias) {
            float4 b = ((const float4*)bias)[c4];
            v.x += b.x; v.y += b.y; v.z += b.z; v.w += b.w;
        }
        ((float4*)C)[gr * 32 + c4] = v;
    }
}

// ---------------- y1 = tanh(A @ hW + b1): warp/row, cp.async staged gathers -----
// Each lane's staged 16B slot is written AND read by the same lane, so only
// cp.async.wait_group ordering is needed (no __syncwarp).
__global__ void spmm_tanh(const float* __restrict__ hW, const int* __restrict__ cols,
                          const float* __restrict__ vals, const float* __restrict__ b1,
                          float* __restrict__ y1, int n)
{
    extern __shared__ char sbuf[];
    int w = (blockIdx.x * blockDim.x + threadIdx.x) >> 5;
    int lane = threadIdx.x & 31;
    int wid  = (threadIdx.x >> 5);
    if (w >= n) return;
    char* wbuf = sbuf + wid * (STAGE * 512) + lane * 16;
    uint32_t wsm = (uint32_t)__cvta_generic_to_shared(wbuf);

    int s = g_rowptr[w], e = g_rowptr[w + 1];
    const float4* H = (const float4*)hW;
    float4 acc = make_float4(0.f, 0.f, 0.f, 0.f);

    for (int base = s; base < e; base += STAGE) {
        int idx = base + lane;
        int   cl = 0; float vl = 0.f;
        if (lane < STAGE && idx < e) { cl = __ldg(&cols[idx]); vl = __ldg(&vals[idx]); }
        int m = min(STAGE, e - base);
        for (int j = 0; j < m; j++) {
            int c = __shfl_sync(0xffffffffu, cl, j);
            cp_async16(wsm + j * 512, &H[c * 32 + lane]);
        }
        cp_async_commit();
        cp_async_wait_all();
        for (int j = 0; j < m; j++) {
            float v = __shfl_sync(0xffffffffu, vl, j);
            float4 h = *(const float4*)(wbuf + j * 512);
            acc.x += v * h.x; acc.y += v * h.y; acc.z += v * h.z; acc.w += v * h.w;
        }
    }
    float4 b = ((const float4*)b1)[lane];
    float4 o = make_float4(tanhf(acc.x + b.x), tanhf(acc.y + b.y),
                           tanhf(acc.z + b.z), tanhf(acc.w + b.w));
    ((float4*)y1)[w * 32 + lane] = o;
}

// ---------------- z = A_rel @ BN2(y1) + BN2(y1)*(ck+1)  (BN2 hoisted) -----------
// sum_e ev*BN2(y1[c]) = s2 * (sum ev*y1[c]) + t2 * (sum ev)
__global__ void spmm_rgin(const float* __restrict__ y1, const int* __restrict__ cols,
                          const float* __restrict__ vals, const int* __restrict__ rel,
                          const float* __restrict__ relc, const float* __restrict__ ck,
                          float* __restrict__ z, int n)
{
    extern __shared__ char sbuf[];
    int w = (blockIdx.x * blockDim.x + threadIdx.x) >> 5;
    int lane = threadIdx.x & 31;
    int wid  = (threadIdx.x >> 5);
    if (w >= n) return;
    char* wbuf = sbuf + wid * (STAGE * 512) + lane * 16;
    uint32_t wsm = (uint32_t)__cvta_generic_to_shared(wbuf);

    int s = g_rowptr[w], e = g_rowptr[w + 1];
    const float4* Y = (const float4*)y1;
    float4 accA = make_float4(0.f, 0.f, 0.f, 0.f);
    float  accB = 0.f;

    for (int base = s; base < e; base += STAGE) {
        int idx = base + lane;
        int cl = 0; float el = 0.f;
        if (lane < STAGE && idx < e) {
            cl = __ldg(&cols[idx]);
            el = __ldg(&vals[idx]) / (__ldg(&relc[__ldg(&rel[idx])]) + 1.f);
        }
        int m = min(STAGE, e - base);
        for (int j = 0; j < m; j++) {
            int c = __shfl_sync(0xffffffffu, cl, j);
            cp_async16(wsm + j * 512, &Y[c * 32 + lane]);
        }
        cp_async_commit();
        cp_async_wait_all();
        for (int j = 0; j < m; j++) {
            float ev = __shfl_sync(0xffffffffu, el, j);
            float4 h = *(const float4*)(wbuf + j * 512);
            accA.x += ev * h.x; accA.y += ev * h.y;
            accA.z += ev * h.z; accA.w += ev * h.w;
            accB += ev;
        }
    }
    int d = lane * 4;
    float4 s2 = *(const float4*)&g_s2[d];
    float4 t2 = *(const float4*)&g_t2[d];
    float4 yr = Y[w * 32 + lane];
    float  cm = __ldg(&ck[w]) + 1.f;
    float4 o;
    o.x = s2.x * accA.x + t2.x * accB + (yr.x * s2.x + t2.x) * cm;
    o.y = s2.y * accA.y + t2.y * accB + (yr.y * s2.y + t2.y) * cm;
    o.z = s2.z * accA.z + t2.z * accB + (yr.z * s2.z + t2.z) * cm;
    o.w = s2.w * accA.w + t2.w * accB + (yr.w * s2.w + t2.w) * cm;
    ((float4*)z)[w * 32 + lane] = o;
}

// ---------------- out = l2n(concat(l2n(x), l2n(y1), l2n(y2))) -------------------
__global__ void final_norm(const float* __restrict__ x, const float* __restrict__ y1,
                           const float* __restrict__ y2, float* __restrict__ out, int n)
{
    int w = (blockIdx.x * blockDim.x + threadIdx.x) >> 5;
    int lane = threadIdx.x & 31;
    if (w >= n) return;
    float4 a = ((const float4*)x )[w * 32 + lane];
    float4 b = ((const float4*)y1)[w * 32 + lane];
    float4 c = ((const float4*)y2)[w * 32 + lane];
    float sa = a.x*a.x + a.y*a.y + a.z*a.z + a.w*a.w;
    float sb = b.x*b.x + b.y*b.y + b.z*b.z + b.w*b.w;
    float sc = c.x*c.x + c.y*c.y + c.z*c.z + c.w*c.w;
    #pragma unroll
    for (int o = 16; o; o >>= 1) {
        sa += __shfl_xor_sync(0xffffffffu, sa, o);
        sb += __shfl_xor_sync(0xffffffffu, sb, o);
        sc += __shfl_xor_sync(0xffffffffu, sc, o);
    }
    float ra = rsqrtf(fmaxf(sa, 1e-12f));
    float rb = rsqrtf(fmaxf(sb, 1e-12f));
    float rc = rsqrtf(fmaxf(sc, 1e-12f));
    float na = sa * ra * ra, nb = sb * rb * rb, nc = sc * rc * rc;
    float rt = rsqrtf(fmaxf(na + nb + nc, 1e-12f));
    float fa = ra * rt, fb = rb * rt, fc = rc * rt;
    float4* O = (float4*)out;
    int base = w * 96;
    O[base + lane]      = make_float4(a.x*fa, a.y*fa, a.z*fa, a.w*fa);
    O[base + 32 + lane] = make_float4(b.x*fb, b.y*fb, b.z*fb, b.w*fb);
    O[base + 64 + lane] = make_float4(c.x*fc, c.y*fc, c.z*fc, c.w*fc);
}

// ---------------- launch --------------------------------------------------------
extern "C" void kernel_launch(void* const* d_in, const int* in_sizes, int n_in,
                              void* d_out, int out_size)
{
    const float* x      = (const float*)d_in[0];
    const int*   rows   = (const int*)  d_in[1];
    const int*   cols   = (const int*)  d_in[2];
    const float* adj    = (const float*)d_in[3];
    const int*   rel    = (const int*)  d_in[4];
    const float* gamma1 = (const float*)d_in[5];
    const float* beta1  = (const float*)d_in[6];
    const float* mean1  = (const float*)d_in[7];
    const float* var1   = (const float*)d_in[8];
    const float* W1     = (const float*)d_in[9];
    const float* b1     = (const float*)d_in[10];
    const float* gamma2 = (const float*)d_in[11];
    const float* beta2  = (const float*)d_in[12];
    const float* mean2  = (const float*)d_in[13];
    const float* var2   = (const float*)d_in[14];
    const float* relc   = (const float*)d_in[15];
    const float* ck     = (const float*)d_in[16];
    const float* Wd     = (const float*)d_in[17];
    const float* bd     = (const float*)d_in[18];
    float* out = (float*)d_out;

    const int n = in_sizes[0] / DIM;     // 50000
    const int e = in_sizes[1];           // 640000

    cudaFuncSetAttribute(gemm128_tf32, cudaFuncAttributeMaxDynamicSharedMemorySize, GEMM_SMEM);
    cudaFuncSetAttribute(spmm_tanh, cudaFuncAttributeMaxDynamicSharedMemorySize, SPMM_SMEM);
    cudaFuncSetAttribute(spmm_rgin, cudaFuncAttributeMaxDynamicSharedMemorySize, SPMM_SMEM);

    // __device__ symbols are NOT valid host-side pointers — fetch device addresses.
    float *hW, *y1, *z, *y2, *s1, *t1;
    cudaGetSymbolAddress((void**)&hW, g_hW);
    cudaGetSymbolAddress((void**)&y1, g_y1);
    cudaGetSymbolAddress((void**)&z,  g_z);
    cudaGetSymbolAddress((void**)&y2, g_y2);
    cudaGetSymbolAddress((void**)&s1, g_s1);
    cudaGetSymbolAddress((void**)&t1, g_t1);

    prep_all<<<(n + 1 + 255) / 256, 256>>>(gamma1, beta1, mean1, var1,
                                           gamma2, beta2, mean2, var2, rows, n, e);

    int gemm_blocks = (n + TM - 1) / TM;
    gemm128_tf32<<<gemm_blocks, 256, GEMM_SMEM>>>(x, W1, hW, s1, t1, nullptr, n);

    int warp_blocks = (n * 32 + 255) / 256;
    spmm_tanh<<<warp_blocks, 256, SPMM_SMEM>>>(hW, cols, adj, b1, y1, n);
    spmm_rgin<<<warp_blocks, 256, SPMM_SMEM>>>(y1, cols, adj, rel, relc, ck, z, n);

    gemm128_tf32<<<gemm_blocks, 256, GEMM_SMEM>>>(z, Wd, y2, nullptr, nullptr, bd, n);

    final_norm<<<warp_blocks, 256>>>(x, y1, y2, out, n);
}

// round 8
// speedup vs baseline: 1.0661x; 1.0661x over previous
#include <cuda_runtime.h>
#include <mma.h>
#include <math.h>
#include <cstdint>

using namespace nvcuda;

// Problem constants (fixed by the dataset)
#define N_NODES 50000
#define DIM     128
#define N_EDGES 640000

// GEMM tiling: block computes 64 rows x 128 cols with tf32 wmma
#define TM 64
#define LDS_PAD 136                       // padded leading dim (mult of 8)
#define GEMM_SMEM ((DIM*LDS_PAD + TM*LDS_PAD) * 4)   // sW 69632 + sA 34816 = 104448 B

// ---------------- scratch (device globals; no allocation allowed) ----------------
__device__ float g_hW[N_NODES*DIM];
__device__ float g_y1[N_NODES*DIM];
__device__ float g_z [N_NODES*DIM];
__device__ float g_y2[N_NODES*DIM];
__device__ int   g_rowptr[N_NODES+1];
__device__ float g_s1[DIM], g_t1[DIM], g_s2[DIM], g_t2[DIM];

// -------- fused: BN folding (block 0) + rowptr build (all blocks) ---------------
__global__ void prep_all(const float* __restrict__ g1, const float* __restrict__ b1,
                         const float* __restrict__ m1, const float* __restrict__ v1,
                         const float* __restrict__ g2, const float* __restrict__ b2,
                         const float* __restrict__ m2, const float* __restrict__ v2,
                         const int* __restrict__ rows, int n, int e)
{
    if (blockIdx.x == 0 && threadIdx.x < DIM) {
        int d = threadIdx.x;
        float s1 = g1[d] * rsqrtf(v1[d] + 1e-3f);
        g_s1[d] = s1; g_t1[d] = b1[d] - m1[d] * s1;
        float s2 = g2[d] * rsqrtf(v2[d] + 1e-3f);
        g_s2[d] = s2; g_t2[d] = b2[d] - m2[d] * s2;
    }
    int r = blockIdx.x * blockDim.x + threadIdx.x;
    if (r > n) return;
    int lo = 0, hi = e;
    while (lo < hi) {
        int mid = (lo + hi) >> 1;
        if (rows[mid] < r) lo = mid + 1; else hi = mid;
    }
    g_rowptr[r] = lo;
}

// ---------------- C[n,128] = (optional BN(A)) @ W (+ optional bias), tf32 wmma --
__global__ void __launch_bounds__(256, 2)
gemm128_tf32(const float* __restrict__ A, const float* __restrict__ W,
             float* __restrict__ C,
             const float* __restrict__ bn_s, const float* __restrict__ bn_t,
             const float* __restrict__ bias, int n)
{
    extern __shared__ float sh[];
    float* sW = sh;                       // [128][136]
    float* sA = sh + DIM * LDS_PAD;       // [64][136]  (reused as epilogue buf)

    const int tid = threadIdx.x;
    const int r0  = blockIdx.x * TM;

    const float4* W4 = (const float4*)W;
    #pragma unroll
    for (int k = 0; k < 16; k++) {
        int idx = tid + k * 256;          // float4 index over 128x128
        float4 w = W4[idx];
        w.x = wmma::__float_to_tf32(w.x);
        w.y = wmma::__float_to_tf32(w.y);
        w.z = wmma::__float_to_tf32(w.z);
        w.w = wmma::__float_to_tf32(w.w);
        int row = idx >> 5, c4 = idx & 31;
        *(float4*)&sW[row * LDS_PAD + c4 * 4] = w;
    }
    #pragma unroll
    for (int k = 0; k < 8; k++) {
        int idx = tid + k * 256;
        int row = idx >> 5, c4 = idx & 31;
        int gr = r0 + row;
        float4 a = make_float4(0.f, 0.f, 0.f, 0.f);
        if (gr < n) {
            a = ((const float4*)A)[gr * 32 + c4];
            if (bn_s) {
                int d = c4 * 4;
                a.x = a.x * bn_s[d + 0] + bn_t[d + 0];
                a.y = a.y * bn_s[d + 1] + bn_t[d + 1];
                a.z = a.z * bn_s[d + 2] + bn_t[d + 2];
                a.w = a.w * bn_s[d + 3] + bn_t[d + 3];
            }
            a.x = wmma::__float_to_tf32(a.x);
            a.y = wmma::__float_to_tf32(a.y);
            a.z = wmma::__float_to_tf32(a.z);
            a.w = wmma::__float_to_tf32(a.w);
        }
        *(float4*)&sA[row * LDS_PAD + c4 * 4] = a;
    }
    __syncthreads();

    const int wid = tid >> 5;
    const int wr  = wid >> 1;            // 0..3 : 16-row group
    const int wc  = wid & 1;             // 0..1 : 64-col group

    wmma::fragment<wmma::accumulator, 16, 16, 8, float> acc[4];
    #pragma unroll
    for (int j = 0; j < 4; j++) wmma::fill_fragment(acc[j], 0.f);

    #pragma unroll
    for (int kk = 0; kk < DIM; kk += 8) {
        wmma::fragment<wmma::matrix_a, 16, 16, 8, wmma::precision::tf32, wmma::row_major> af;
        wmma::load_matrix_sync(af, &sA[(wr * 16) * LDS_PAD + kk], LDS_PAD);
        #pragma unroll
        for (int j = 0; j < 4; j++) {
            wmma::fragment<wmma::matrix_b, 16, 16, 8, wmma::precision::tf32, wmma::row_major> bf;
            wmma::load_matrix_sync(bf, &sW[kk * LDS_PAD + wc * 64 + j * 16], LDS_PAD);
            wmma::mma_sync(acc[j], af, bf, acc[j]);
        }
    }

    __syncthreads();   // everyone done reading sA
    #pragma unroll
    for (int j = 0; j < 4; j++)
        wmma::store_matrix_sync(&sA[(wr * 16) * LDS_PAD + wc * 64 + j * 16],
                                acc[j], LDS_PAD, wmma::mem_row_major);
    __syncthreads();

    #pragma unroll
    for (int k = 0; k < 8; k++) {
        int idx = tid + k * 256;          // 2048 float4 over 64x128
        int row = idx >> 5, c4 = idx & 31;
        int gr = r0 + row;
        if (gr >= n) continue;
        float4 v = *(float4*)&sA[row * LDS_PAD + c4 * 4];
        if (bias) {
            float4 b = ((const float4*)bias)[c4];
            v.x += b.x; v.y += b.y; v.z += b.z; v.w += b.w;
        }
        ((float4*)C)[gr * 32 + c4] = v;
    }
}

// ---------------- y1 = tanh(A @ hW + b1): warp per TWO rows, interleaved --------
// Two independent accumulation chains per warp double gather-MLP without the
// register blowup of deep unrolling. Per-row accumulation order unchanged.
__global__ void spmm_tanh(const float* __restrict__ hW, const int* __restrict__ cols,
                          const float* __restrict__ vals, const float* __restrict__ b1,
                          float* __restrict__ y1, int n)
{
    int wp   = (blockIdx.x * blockDim.x + threadIdx.x) >> 5;
    int lane = threadIdx.x & 31;
    int r0 = wp * 2, r1 = r0 + 1;
    if (r0 >= n) return;
    bool has1 = (r1 < n);

    int s0 = g_rowptr[r0], e0 = g_rowptr[r0 + 1];
    int len0 = e0 - s0;
    int s1 = 0, len1 = 0;
    if (has1) { s1 = e0; len1 = g_rowptr[r1 + 1] - e0; }

    const float4* H = (const float4*)hW;
    float4 acc0 = make_float4(0.f, 0.f, 0.f, 0.f);
    float4 acc1 = make_float4(0.f, 0.f, 0.f, 0.f);

    int maxlen = max(len0, len1);
    for (int base = 0; base < maxlen; base += 32) {
        int k = base + lane;
        int c0l = 0, c1l = 0; float v0l = 0.f, v1l = 0.f;
        if (k < len0) { c0l = __ldg(&cols[s0 + k]); v0l = __ldg(&vals[s0 + k]); }
        if (k < len1) { c1l = __ldg(&cols[s1 + k]); v1l = __ldg(&vals[s1 + k]); }
        int m0 = min(32, len0 - base); m0 = max(m0, 0);
        int m1 = min(32, len1 - base); m1 = max(m1, 0);
        int mm = max(m0, m1);
        for (int j = 0; j < mm; j++) {
            int   ca = __shfl_sync(0xffffffffu, c0l, j);
            float va = __shfl_sync(0xffffffffu, v0l, j);
            int   cb = __shfl_sync(0xffffffffu, c1l, j);
            float vb = __shfl_sync(0xffffffffu, v1l, j);
            float4 ha, hb;
            bool p0 = (j < m0), p1 = (j < m1);
            if (p0) ha = H[ca * 32 + lane];
            if (p1) hb = H[cb * 32 + lane];
            if (p0) { acc0.x += va * ha.x; acc0.y += va * ha.y;
                      acc0.z += va * ha.z; acc0.w += va * ha.w; }
            if (p1) { acc1.x += vb * hb.x; acc1.y += vb * hb.y;
                      acc1.z += vb * hb.z; acc1.w += vb * hb.w; }
        }
    }
    float4 b = ((const float4*)b1)[lane];
    ((float4*)y1)[r0 * 32 + lane] =
        make_float4(tanhf(acc0.x + b.x), tanhf(acc0.y + b.y),
                    tanhf(acc0.z + b.z), tanhf(acc0.w + b.w));
    if (has1)
        ((float4*)y1)[r1 * 32 + lane] =
            make_float4(tanhf(acc1.x + b.x), tanhf(acc1.y + b.y),
                        tanhf(acc1.z + b.z), tanhf(acc1.w + b.w));
}

// ---------------- z = A_rel @ BN2(y1) + BN2(y1)*(ck+1): two rows per warp -------
// sum_e ev*BN2(y1[c]) = s2 * (sum ev*y1[c]) + t2 * (sum ev)
__global__ void spmm_rgin(const float* __restrict__ y1, const int* __restrict__ cols,
                          const float* __restrict__ vals, const int* __restrict__ rel,
                          const float* __restrict__ relc, const float* __restrict__ ck,
                          float* __restrict__ z, int n)
{
    int wp   = (blockIdx.x * blockDim.x + threadIdx.x) >> 5;
    int lane = threadIdx.x & 31;
    int r0 = wp * 2, r1 = r0 + 1;
    if (r0 >= n) return;
    bool has1 = (r1 < n);

    int s0 = g_rowptr[r0], e0 = g_rowptr[r0 + 1];
    int len0 = e0 - s0;
    int s1 = 0, len1 = 0;
    if (has1) { s1 = e0; len1 = g_rowptr[r1 + 1] - e0; }

    const float4* Y = (const float4*)y1;
    float4 accA0 = make_float4(0.f, 0.f, 0.f, 0.f);
    float4 accA1 = make_float4(0.f, 0.f, 0.f, 0.f);
    float  accB0 = 0.f, accB1 = 0.f;

    int maxlen = max(len0, len1);
    for (int base = 0; base < maxlen; base += 32) {
        int k = base + lane;
        int c0l = 0, c1l = 0; float e0l = 0.f, e1l = 0.f;
        if (k < len0) {
            c0l = __ldg(&cols[s0 + k]);
            e0l = __ldg(&vals[s0 + k]) / (__ldg(&relc[__ldg(&rel[s0 + k])]) + 1.f);
        }
        if (k < len1) {
            c1l = __ldg(&cols[s1 + k]);
            e1l = __ldg(&vals[s1 + k]) / (__ldg(&relc[__ldg(&rel[s1 + k])]) + 1.f);
        }
        int m0 = min(32, len0 - base); m0 = max(m0, 0);
        int m1 = min(32, len1 - base); m1 = max(m1, 0);
        int mm = max(m0, m1);
        for (int j = 0; j < mm; j++) {
            int   ca = __shfl_sync(0xffffffffu, c0l, j);
            float ea = __shfl_sync(0xffffffffu, e0l, j);
            int   cb = __shfl_sync(0xffffffffu, c1l, j);
            float eb = __shfl_sync(0xffffffffu, e1l, j);
            float4 ha, hb;
            bool p0 = (j < m0), p1 = (j < m1);
            if (p0) ha = Y[ca * 32 + lane];
            if (p1) hb = Y[cb * 32 + lane];
            if (p0) { accA0.x += ea * ha.x; accA0.y += ea * ha.y;
                      accA0.z += ea * ha.z; accA0.w += ea * ha.w; accB0 += ea; }
            if (p1) { accA1.x += eb * hb.x; accA1.y += eb * hb.y;
                      accA1.z += eb * hb.z; accA1.w += eb * hb.w; accB1 += eb; }
        }
    }
    int d = lane * 4;
    float4 s2 = *(const float4*)&g_s2[d];
    float4 t2 = *(const float4*)&g_t2[d];
    {
        float4 yr = Y[r0 * 32 + lane];
        float  cm = __ldg(&ck[r0]) + 1.f;
        float4 o;
        o.x = s2.x * accA0.x + t2.x * accB0 + (yr.x * s2.x + t2.x) * cm;
        o.y = s2.y * accA0.y + t2.y * accB0 + (yr.y * s2.y + t2.y) * cm;
        o.z = s2.z * accA0.z + t2.z * accB0 + (yr.z * s2.z + t2.z) * cm;
        o.w = s2.w * accA0.w + t2.w * accB0 + (yr.w * s2.w + t2.w) * cm;
        ((float4*)z)[r0 * 32 + lane] = o;
    }
    if (has1) {
        float4 yr = Y[r1 * 32 + lane];
        float  cm = __ldg(&ck[r1]) + 1.f;
        float4 o;
        o.x = s2.x * accA1.x + t2.x * accB1 + (yr.x * s2.x + t2.x) * cm;
        o.y = s2.y * accA1.y + t2.y * accB1 + (yr.y * s2.y + t2.y) * cm;
        o.z = s2.z * accA1.z + t2.z * accB1 + (yr.z * s2.z + t2.z) * cm;
        o.w = s2.w * accA1.w + t2.w * accB1 + (yr.w * s2.w + t2.w) * cm;
        ((float4*)z)[r1 * 32 + lane] = o;
    }
}

// ---------------- out = l2n(concat(l2n(x), l2n(y1), l2n(y2))) -------------------
__global__ void final_norm(const float* __restrict__ x, const float* __restrict__ y1,
                           const float* __restrict__ y2, float* __restrict__ out, int n)
{
    int w = (blockIdx.x * blockDim.x + threadIdx.x) >> 5;
    int lane = threadIdx.x & 31;
    if (w >= n) return;
    float4 a = ((const float4*)x )[w * 32 + lane];
    float4 b = ((const float4*)y1)[w * 32 + lane];
    float4 c = ((const float4*)y2)[w * 32 + lane];
    float sa = a.x*a.x + a.y*a.y + a.z*a.z + a.w*a.w;
    float sb = b.x*b.x + b.y*b.y + b.z*b.z + b.w*b.w;
    float sc = c.x*c.x + c.y*c.y + c.z*c.z + c.w*c.w;
    #pragma unroll
    for (int o = 16; o; o >>= 1) {
        sa += __shfl_xor_sync(0xffffffffu, sa, o);
        sb += __shfl_xor_sync(0xffffffffu, sb, o);
        sc += __shfl_xor_sync(0xffffffffu, sc, o);
    }
    float ra = rsqrtf(fmaxf(sa, 1e-12f));
    float rb = rsqrtf(fmaxf(sb, 1e-12f));
    float rc = rsqrtf(fmaxf(sc, 1e-12f));
    float na = sa * ra * ra, nb = sb * rb * rb, nc = sc * rc * rc;
    float rt = rsqrtf(fmaxf(na + nb + nc, 1e-12f));
    float fa = ra * rt, fb = rb * rt, fc = rc * rt;
    float4* O = (float4*)out;
    int base = w * 96;
    O[base + lane]      = make_float4(a.x*fa, a.y*fa, a.z*fa, a.w*fa);
    O[base + 32 + lane] = make_float4(b.x*fb, b.y*fb, b.z*fb, b.w*fb);
    O[base + 64 + lane] = make_float4(c.x*fc, c.y*fc, c.z*fc, c.w*fc);
}

// ---------------- launch --------------------------------------------------------
extern "C" void kernel_launch(void* const* d_in, const int* in_sizes, int n_in,
                              void* d_out, int out_size)
{
    const float* x      = (const float*)d_in[0];
    const int*   rows   = (const int*)  d_in[1];
    const int*   cols   = (const int*)  d_in[2];
    const float* adj    = (const float*)d_in[3];
    const int*   rel    = (const int*)  d_in[4];
    const float* gamma1 = (const float*)d_in[5];
    const float* beta1  = (const float*)d_in[6];
    const float* mean1  = (const float*)d_in[7];
    const float* var1   = (const float*)d_in[8];
    const float* W1     = (const float*)d_in[9];
    const float* b1     = (const float*)d_in[10];
    const float* gamma2 = (const float*)d_in[11];
    const float* beta2  = (const float*)d_in[12];
    const float* mean2  = (const float*)d_in[13];
    const float* var2   = (const float*)d_in[14];
    const float* relc   = (const float*)d_in[15];
    const float* ck     = (const float*)d_in[16];
    const float* Wd     = (const float*)d_in[17];
    const float* bd     = (const float*)d_in[18];
    float* out = (float*)d_out;

    const int n = in_sizes[0] / DIM;     // 50000
    const int e = in_sizes[1];           // 640000

    cudaFuncSetAttribute(gemm128_tf32, cudaFuncAttributeMaxDynamicSharedMemorySize, GEMM_SMEM);

    // __device__ symbols are NOT valid host-side pointers — fetch device addresses.
    float *hW, *y1, *z, *y2, *s1, *t1;
    cudaGetSymbolAddress((void**)&hW, g_hW);
    cudaGetSymbolAddress((void**)&y1, g_y1);
    cudaGetSymbolAddress((void**)&z,  g_z);
    cudaGetSymbolAddress((void**)&y2, g_y2);
    cudaGetSymbolAddress((void**)&s1, g_s1);
    cudaGetSymbolAddress((void**)&t1, g_t1);

    prep_all<<<(n + 1 + 255) / 256, 256>>>(gamma1, beta1, mean1, var1,
                                           gamma2, beta2, mean2, var2, rows, n, e);

    int gemm_blocks = (n + TM - 1) / TM;
    gemm128_tf32<<<gemm_blocks, 256, GEMM_SMEM>>>(x, W1, hW, s1, t1, nullptr, n);

    int npairs = (n + 1) / 2;
    int pair_blocks = (npairs * 32 + 255) / 256;
    spmm_tanh<<<pair_blocks, 256>>>(hW, cols, adj, b1, y1, n);
    spmm_rgin<<<pair_blocks, 256>>>(y1, cols, adj, rel, relc, ck, z, n);

    gemm128_tf32<<<gemm_blocks, 256, GEMM_SMEM>>>(z, Wd, y2, nullptr, nullptr, bd, n);

    int warp_blocks = (n * 32 + 255) / 256;
    final_norm<<<warp_blocks, 256>>>(x, y1, y2, out, n);
}

// round 9
// speedup vs baseline: 1.1089x; 1.0401x over previous
#include <cuda_runtime.h>
#include <mma.h>
#include <math.h>
#include <cstdint>

using namespace nvcuda;

// Problem constants (fixed by the dataset)
#define N_NODES 50000
#define DIM     128
#define N_EDGES 640000

// GEMM tiling: block computes 64 rows x 128 cols with tf32 wmma
#define TM 64
#define LDS_PAD 136                       // padded leading dim (mult of 8)
#define GEMM_SMEM ((DIM*LDS_PAD + TM*LDS_PAD) * 4)   // sW 69632 + sA 34816 = 104448 B

// ---------------- scratch (device globals; no allocation allowed) ----------------
__device__ float g_hW[N_NODES*DIM];
__device__ float g_y1[N_NODES*DIM];
__device__ float g_z [N_NODES*DIM];
__device__ float g_ev[N_EDGES];
__device__ int   g_rowptr[N_NODES+1];
__device__ float g_s1[DIM], g_t1[DIM], g_s2[DIM], g_t2[DIM];

// ---------------- 1: BN folding: s = gamma*rsqrt(var+eps), t = beta - mean*s ----
__global__ void prep_bn(const float* __restrict__ g1, const float* __restrict__ b1,
                        const float* __restrict__ m1, const float* __restrict__ v1,
                        const float* __restrict__ g2, const float* __restrict__ b2,
                        const float* __restrict__ m2, const float* __restrict__ v2)
{
    int d = threadIdx.x;
    float s1 = g1[d] * rsqrtf(v1[d] + 1e-3f);
    g_s1[d] = s1; g_t1[d] = b1[d] - m1[d] * s1;
    float s2 = g2[d] * rsqrtf(v2[d] + 1e-3f);
    g_s2[d] = s2; g_t2[d] = b2[d] - m2[d] * s2;
}

// ---------------- 2: rowptr (rows sorted; lower_bound per dest row) -------------
__global__ void build_rowptr(const int* __restrict__ rows, int n, int e)
{
    int r = blockIdx.x * blockDim.x + threadIdx.x;
    if (r > n) return;
    int lo = 0, hi = e;
    while (lo < hi) {
        int mid = (lo + hi) >> 1;
        if (rows[mid] < r) lo = mid + 1; else hi = mid;
    }
    g_rowptr[r] = lo;
}

// ---------------- 3: per-edge relation weights ev = adj/(relc[rel]+1) -----------
__global__ void edge_ev(const float* __restrict__ vals, const int* __restrict__ rel,
                        const float* __restrict__ relc, int e)
{
    int i = blockIdx.x * blockDim.x + threadIdx.x;
    if (i >= e) return;
    g_ev[i] = vals[i] / (relc[rel[i]] + 1.f);
}

// ---------------- 4: C[n,128] = (optional BN(A)) @ W, tf32 wmma -----------------
__global__ void __launch_bounds__(256, 2)
gemm128_tf32(const float* __restrict__ A, const float* __restrict__ W,
             float* __restrict__ C,
             const float* __restrict__ bn_s, const float* __restrict__ bn_t, int n)
{
    extern __shared__ float sh[];
    float* sW = sh;                       // [128][136]
    float* sA = sh + DIM * LDS_PAD;       // [64][136]  (reused as epilogue buf)

    const int tid = threadIdx.x;
    const int r0  = blockIdx.x * TM;

    const float4* W4 = (const float4*)W;
    #pragma unroll
    for (int k = 0; k < 16; k++) {
        int idx = tid + k * 256;          // float4 index over 128x128
        float4 w = W4[idx];
        w.x = wmma::__float_to_tf32(w.x);
        w.y = wmma::__float_to_tf32(w.y);
        w.z = wmma::__float_to_tf32(w.z);
        w.w = wmma::__float_to_tf32(w.w);
        int row = idx >> 5, c4 = idx & 31;
        *(float4*)&sW[row * LDS_PAD + c4 * 4] = w;
    }
    #pragma unroll
    for (int k = 0; k < 8; k++) {
        int idx = tid + k * 256;
        int row = idx >> 5, c4 = idx & 31;
        int gr = r0 + row;
        float4 a = make_float4(0.f, 0.f, 0.f, 0.f);
        if (gr < n) {
            a = ((const float4*)A)[gr * 32 + c4];
            if (bn_s) {
                int d = c4 * 4;
                a.x = a.x * bn_s[d + 0] + bn_t[d + 0];
                a.y = a.y * bn_s[d + 1] + bn_t[d + 1];
                a.z = a.z * bn_s[d + 2] + bn_t[d + 2];
                a.w = a.w * bn_s[d + 3] + bn_t[d + 3];
            }
            a.x = wmma::__float_to_tf32(a.x);
            a.y = wmma::__float_to_tf32(a.y);
            a.z = wmma::__float_to_tf32(a.z);
            a.w = wmma::__float_to_tf32(a.w);
        }
        *(float4*)&sA[row * LDS_PAD + c4 * 4] = a;
    }
    __syncthreads();

    const int wid = tid >> 5;
    const int wr  = wid >> 1;            // 0..3 : 16-row group
    const int wc  = wid & 1;             // 0..1 : 64-col group

    wmma::fragment<wmma::accumulator, 16, 16, 8, float> acc[4];
    #pragma unroll
    for (int j = 0; j < 4; j++) wmma::fill_fragment(acc[j], 0.f);

    #pragma unroll
    for (int kk = 0; kk < DIM; kk += 8) {
        wmma::fragment<wmma::matrix_a, 16, 16, 8, wmma::precision::tf32, wmma::row_major> af;
        wmma::load_matrix_sync(af, &sA[(wr * 16) * LDS_PAD + kk], LDS_PAD);
        #pragma unroll
        for (int j = 0; j < 4; j++) {
            wmma::fragment<wmma::matrix_b, 16, 16, 8, wmma::precision::tf32, wmma::row_major> bf;
            wmma::load_matrix_sync(bf, &sW[kk * LDS_PAD + wc * 64 + j * 16], LDS_PAD);
            wmma::mma_sync(acc[j], af, bf, acc[j]);
        }
    }

    __syncthreads();
    #pragma unroll
    for (int j = 0; j < 4; j++)
        wmma::store_matrix_sync(&sA[(wr * 16) * LDS_PAD + wc * 64 + j * 16],
                                acc[j], LDS_PAD, wmma::mem_row_major);
    __syncthreads();

    #pragma unroll
    for (int k = 0; k < 8; k++) {
        int idx = tid + k * 256;          // 2048 float4 over 64x128
        int row = idx >> 5, c4 = idx & 31;
        int gr = r0 + row;
        if (gr >= n) continue;
        ((float4*)C)[gr * 32 + c4] = *(float4*)&sA[row * LDS_PAD + c4 * 4];
    }
}

// --------- 7: gemm2 (z @ Wd + bd) FUSED with final l2-normalize-concat ----------
// out[r] = l2n(concat(l2n(x_r), l2n(y1_r), l2n(y2_r))), y2_r computed in-block.
__global__ void __launch_bounds__(256, 2)
gemm128_norm(const float* __restrict__ A, const float* __restrict__ W,
             const float* __restrict__ bias,
             const float* __restrict__ x, const float* __restrict__ y1,
             float* __restrict__ out, int n)
{
    extern __shared__ float sh[];
    float* sW = sh;
    float* sA = sh + DIM * LDS_PAD;

    const int tid = threadIdx.x;
    const int r0  = blockIdx.x * TM;

    const float4* W4 = (const float4*)W;
    #pragma unroll
    for (int k = 0; k < 16; k++) {
        int idx = tid + k * 256;
        float4 w = W4[idx];
        w.x = wmma::__float_to_tf32(w.x);
        w.y = wmma::__float_to_tf32(w.y);
        w.z = wmma::__float_to_tf32(w.z);
        w.w = wmma::__float_to_tf32(w.w);
        int row = idx >> 5, c4 = idx & 31;
        *(float4*)&sW[row * LDS_PAD + c4 * 4] = w;
    }
    #pragma unroll
    for (int k = 0; k < 8; k++) {
        int idx = tid + k * 256;
        int row = idx >> 5, c4 = idx & 31;
        int gr = r0 + row;
        float4 a = make_float4(0.f, 0.f, 0.f, 0.f);
        if (gr < n) {
            a = ((const float4*)A)[gr * 32 + c4];
            a.x = wmma::__float_to_tf32(a.x);
            a.y = wmma::__float_to_tf32(a.y);
            a.z = wmma::__float_to_tf32(a.z);
            a.w = wmma::__float_to_tf32(a.w);
        }
        *(float4*)&sA[row * LDS_PAD + c4 * 4] = a;
    }
    __syncthreads();

    const int wid = tid >> 5;
    const int wr  = wid >> 1;
    const int wc  = wid & 1;

    wmma::fragment<wmma::accumulator, 16, 16, 8, float> acc[4];
    #pragma unroll
    for (int j = 0; j < 4; j++) wmma::fill_fragment(acc[j], 0.f);

    #pragma unroll
    for (int kk = 0; kk < DIM; kk += 8) {
        wmma::fragment<wmma::matrix_a, 16, 16, 8, wmma::precision::tf32, wmma::row_major> af;
        wmma::load_matrix_sync(af, &sA[(wr * 16) * LDS_PAD + kk], LDS_PAD);
        #pragma unroll
        for (int j = 0; j < 4; j++) {
            wmma::fragment<wmma::matrix_b, 16, 16, 8, wmma::precision::tf32, wmma::row_major> bf;
            wmma::load_matrix_sync(bf, &sW[kk * LDS_PAD + wc * 64 + j * 16], LDS_PAD);
            wmma::mma_sync(acc[j], af, bf, acc[j]);
        }
    }

    __syncthreads();
    #pragma unroll
    for (int j = 0; j < 4; j++)
        wmma::store_matrix_sync(&sA[(wr * 16) * LDS_PAD + wc * 64 + j * 16],
                                acc[j], LDS_PAD, wmma::mem_row_major);
    __syncthreads();

    // epilogue: warp wid handles rows wid*8 .. wid*8+7; lane = col-group of 4
    const int lane = tid & 31;
    float4 bv = ((const float4*)bias)[lane];
    #pragma unroll
    for (int rr = 0; rr < 8; rr++) {
        int row = wid * 8 + rr;
        int gr  = r0 + row;
        if (gr >= n) continue;
        float4 c = *(float4*)&sA[row * LDS_PAD + lane * 4];
        c.x += bv.x; c.y += bv.y; c.z += bv.z; c.w += bv.w;
        float4 a = ((const float4*)x )[gr * 32 + lane];
        float4 b = ((const float4*)y1)[gr * 32 + lane];
        float sa = a.x*a.x + a.y*a.y + a.z*a.z + a.w*a.w;
        float sb = b.x*b.x + b.y*b.y + b.z*b.z + b.w*b.w;
        float sc = c.x*c.x + c.y*c.y + c.z*c.z + c.w*c.w;
        #pragma unroll
        for (int o = 16; o; o >>= 1) {
            sa += __shfl_xor_sync(0xffffffffu, sa, o);
            sb += __shfl_xor_sync(0xffffffffu, sb, o);
            sc += __shfl_xor_sync(0xffffffffu, sc, o);
        }
        float ra = rsqrtf(fmaxf(sa, 1e-12f));
        float rb = rsqrtf(fmaxf(sb, 1e-12f));
        float rc = rsqrtf(fmaxf(sc, 1e-12f));
        float na = sa * ra * ra, nb = sb * rb * rb, nc = sc * rc * rc;
        float rt = rsqrtf(fmaxf(na + nb + nc, 1e-12f));
        float fa = ra * rt, fb = rb * rt, fc = rc * rt;
        float4* O = (float4*)out;
        int obase = gr * 96;
        O[obase + lane]      = make_float4(a.x*fa, a.y*fa, a.z*fa, a.w*fa);
        O[obase + 32 + lane] = make_float4(b.x*fb, b.y*fb, b.z*fb, b.w*fb);
        O[obase + 64 + lane] = make_float4(c.x*fc, c.y*fc, c.z*fc, c.w*fc);
    }
}

// ---------------- 5: y1 = tanh(A @ hW + b1): warp/row, 4-deep gather pipeline ---
__global__ void spmm_tanh(const float* __restrict__ hW, const int* __restrict__ cols,
                          const float* __restrict__ vals, const float* __restrict__ b1,
                          float* __restrict__ y1, int n)
{
    int w = (blockIdx.x * blockDim.x + threadIdx.x) >> 5;
    int lane = threadIdx.x & 31;
    if (w >= n) return;
    int s = g_rowptr[w], e = g_rowptr[w + 1];
    const float4* H = (const float4*)hW;
    float4 acc = make_float4(0.f, 0.f, 0.f, 0.f);
    for (int base = s; base < e; base += 32) {
        int idx = base + lane;
        int   cl = 0; float vl = 0.f;
        if (idx < e) { cl = __ldg(&cols[idx]); vl = __ldg(&vals[idx]); }
        int m = min(32, e - base);
        int j = 0;
        for (; j + 4 <= m; j += 4) {
            int   c0 = __shfl_sync(0xffffffffu, cl, j);
            int   c1 = __shfl_sync(0xffffffffu, cl, j + 1);
            int   c2 = __shfl_sync(0xffffffffu, cl, j + 2);
            int   c3 = __shfl_sync(0xffffffffu, cl, j + 3);
            float v0 = __shfl_sync(0xffffffffu, vl, j);
            float v1 = __shfl_sync(0xffffffffu, vl, j + 1);
            float v2 = __shfl_sync(0xffffffffu, vl, j + 2);
            float v3 = __shfl_sync(0xffffffffu, vl, j + 3);
            float4 h0 = H[c0 * 32 + lane];
            float4 h1 = H[c1 * 32 + lane];
            float4 h2 = H[c2 * 32 + lane];
            float4 h3 = H[c3 * 32 + lane];
            acc.x += v0 * h0.x + v1 * h1.x + v2 * h2.x + v3 * h3.x;
            acc.y += v0 * h0.y + v1 * h1.y + v2 * h2.y + v3 * h3.y;
            acc.z += v0 * h0.z + v1 * h1.z + v2 * h2.z + v3 * h3.z;
            acc.w += v0 * h0.w + v1 * h1.w + v2 * h2.w + v3 * h3.w;
        }
        for (; j < m; j++) {
            int   c = __shfl_sync(0xffffffffu, cl, j);
            float v = __shfl_sync(0xffffffffu, vl, j);
            float4 h = H[c * 32 + lane];
            acc.x += v * h.x; acc.y += v * h.y; acc.z += v * h.z; acc.w += v * h.w;
        }
    }
    float4 b = ((const float4*)b1)[lane];
    float4 o = make_float4(tanhf(acc.x + b.x), tanhf(acc.y + b.y),
                           tanhf(acc.z + b.z), tanhf(acc.w + b.w));
    ((float4*)y1)[w * 32 + lane] = o;
}

// ---------------- 6: z = A_rel @ BN2(y1) + BN2(y1)*(ck+1)  (ev precomputed) -----
__global__ void spmm_rgin(const float* __restrict__ y1, const int* __restrict__ cols,
                          const float* __restrict__ ev, const float* __restrict__ ck,
                          float* __restrict__ z, int n)
{
    int w = (blockIdx.x * blockDim.x + threadIdx.x) >> 5;
    int lane = threadIdx.x & 31;
    if (w >= n) return;
    int s = g_rowptr[w], e = g_rowptr[w + 1];
    const float4* Y = (const float4*)y1;
    float4 accA = make_float4(0.f, 0.f, 0.f, 0.f);
    float  accB = 0.f;
    for (int base = s; base < e; base += 32) {
        int idx = base + lane;
        int cl = 0; float el = 0.f;
        if (idx < e) { cl = __ldg(&cols[idx]); el = __ldg(&ev[idx]); }
        int m = min(32, e - base);
        int j = 0;
        for (; j + 4 <= m; j += 4) {
            int   c0 = __shfl_sync(0xffffffffu, cl, j);
            int   c1 = __shfl_sync(0xffffffffu, cl, j + 1);
            int   c2 = __shfl_sync(0xffffffffu, cl, j + 2);
            int   c3 = __shfl_sync(0xffffffffu, cl, j + 3);
            float e0 = __shfl_sync(0xffffffffu, el, j);
            float e1 = __shfl_sync(0xffffffffu, el, j + 1);
            float e2 = __shfl_sync(0xffffffffu, el, j + 2);
            float e3 = __shfl_sync(0xffffffffu, el, j + 3);
            float4 h0 = Y[c0 * 32 + lane];
            float4 h1 = Y[c1 * 32 + lane];
            float4 h2 = Y[c2 * 32 + lane];
            float4 h3 = Y[c3 * 32 + lane];
            accA.x += e0 * h0.x + e1 * h1.x + e2 * h2.x + e3 * h3.x;
            accA.y += e0 * h0.y + e1 * h1.y + e2 * h2.y + e3 * h3.y;
            accA.z += e0 * h0.z + e1 * h1.z + e2 * h2.z + e3 * h3.z;
            accA.w += e0 * h0.w + e1 * h1.w + e2 * h2.w + e3 * h3.w;
            accB += e0 + e1 + e2 + e3;
        }
        for (; j < m; j++) {
            int   c  = __shfl_sync(0xffffffffu, cl, j);
            float ee = __shfl_sync(0xffffffffu, el, j);
            float4 h = Y[c * 32 + lane];
            accA.x += ee * h.x; accA.y += ee * h.y;
            accA.z += ee * h.z; accA.w += ee * h.w;
            accB += ee;
        }
    }
    int d = lane * 4;
    float4 s2 = *(const float4*)&g_s2[d];
    float4 t2 = *(const float4*)&g_t2[d];
    float4 yr = Y[w * 32 + lane];
    float  cm = __ldg(&ck[w]) + 1.f;
    float4 o;
    o.x = s2.x * accA.x + t2.x * accB + (yr.x * s2.x + t2.x) * cm;
    o.y = s2.y * accA.y + t2.y * accB + (yr.y * s2.y + t2.y) * cm;
    o.z = s2.z * accA.z + t2.z * accB + (yr.z * s2.z + t2.z) * cm;
    o.w = s2.w * accA.w + t2.w * accB + (yr.w * s2.w + t2.w) * cm;
    ((float4*)z)[w * 32 + lane] = o;
}

// ---------------- launch --------------------------------------------------------
extern "C" void kernel_launch(void* const* d_in, const int* in_sizes, int n_in,
                              void* d_out, int out_size)
{
    const float* x      = (const float*)d_in[0];
    const int*   rows   = (const int*)  d_in[1];
    const int*   cols   = (const int*)  d_in[2];
    const float* adj    = (const float*)d_in[3];
    const int*   rel    = (const int*)  d_in[4];
    const float* gamma1 = (const float*)d_in[5];
    const float* beta1  = (const float*)d_in[6];
    const float* mean1  = (const float*)d_in[7];
    const float* var1   = (const float*)d_in[8];
    const float* W1     = (const float*)d_in[9];
    const float* b1     = (const float*)d_in[10];
    const float* gamma2 = (const float*)d_in[11];
    const float* beta2  = (const float*)d_in[12];
    const float* mean2  = (const float*)d_in[13];
    const float* var2   = (const float*)d_in[14];
    const float* relc   = (const float*)d_in[15];
    const float* ck     = (const float*)d_in[16];
    const float* Wd     = (const float*)d_in[17];
    const float* bd     = (const float*)d_in[18];
    float* out = (float*)d_out;

    const int n = in_sizes[0] / DIM;     // 50000
    const int e = in_sizes[1];           // 640000

    cudaFuncSetAttribute(gemm128_tf32, cudaFuncAttributeMaxDynamicSharedMemorySize, GEMM_SMEM);
    cudaFuncSetAttribute(gemm128_norm, cudaFuncAttributeMaxDynamicSharedMemorySize, GEMM_SMEM);

    // __device__ symbols are NOT valid host-side pointers — fetch device addresses.
    float *hW, *y1, *z, *ev, *s1, *t1;
    cudaGetSymbolAddress((void**)&hW, g_hW);
    cudaGetSymbolAddress((void**)&y1, g_y1);
    cudaGetSymbolAddress((void**)&z,  g_z);
    cudaGetSymbolAddress((void**)&ev, g_ev);
    cudaGetSymbolAddress((void**)&s1, g_s1);
    cudaGetSymbolAddress((void**)&t1, g_t1);

    // launch order matters for ncu visibility: gemm128_tf32 is launch #4
    prep_bn<<<1, DIM>>>(gamma1, beta1, mean1, var1, gamma2, beta2, mean2, var2);
    build_rowptr<<<(n + 1 + 255) / 256, 256>>>(rows, n, e);
    edge_ev<<<(e + 255) / 256, 256>>>(adj, rel, relc, e);

    int gemm_blocks = (n + TM - 1) / TM;
    gemm128_tf32<<<gemm_blocks, 256, GEMM_SMEM>>>(x, W1, hW, s1, t1, n);

    int warp_blocks = (n * 32 + 255) / 256;
    spmm_tanh<<<warp_blocks, 256>>>(hW, cols, adj, b1, y1, n);
    spmm_rgin<<<warp_blocks, 256>>>(y1, cols, ev, ck, z, n);

    gemm128_norm<<<gemm_blocks, 256, GEMM_SMEM>>>(z, Wd, bd, x, y1, out, n);
}

// round 10
// speedup vs baseline: 1.1322x; 1.0210x over previous
#include <cuda_runtime.h>
#include <mma.h>
#include <math.h>
#include <cstdint>

using namespace nvcuda;

// Problem constants (fixed by the dataset)
#define N_NODES 50000
#define DIM     128
#define N_EDGES 640000

// GEMM tiling: block computes 64 rows x 128 cols with tf32 wmma
#define TM 64
#define LDS_PAD 136                       // padded leading dim (mult of 8; 136*4=544=34*16B ok for cp.async)
#define GEMM_SMEM ((DIM*LDS_PAD + TM*LDS_PAD) * 4)   // sW 69632 + sA 34816 = 104448 B

// ---------------- scratch (device globals; no allocation allowed) ----------------
__device__ float g_hW[N_NODES*DIM];
__device__ float g_y1[N_NODES*DIM];
__device__ float g_z [N_NODES*DIM];
__device__ float g_ev[N_EDGES];
__device__ float g_W1t[DIM*DIM];          // tf32-rounded W1
__device__ float g_Wdt[DIM*DIM];          // tf32-rounded Wd
__device__ int   g_rowptr[N_NODES+1];
__device__ float g_s1[DIM], g_t1[DIM], g_s2[DIM], g_t2[DIM];

__device__ __forceinline__ void cp_async16(uint32_t smem_addr, const void* gptr) {
    asm volatile("cp.async.cg.shared.global [%0], [%1], 16;\n"
                 :: "r"(smem_addr), "l"(gptr) : "memory");
}
__device__ __forceinline__ void cp_async_commit() {
    asm volatile("cp.async.commit_group;\n" ::: "memory");
}
__device__ __forceinline__ void cp_async_wait_all() {
    asm volatile("cp.async.wait_group 0;\n" ::: "memory");
}

// ---------------- 1: BN folding + W tf32 pre-conversion -------------------------
__global__ void prep_bn_w(const float* __restrict__ g1, const float* __restrict__ b1,
                          const float* __restrict__ m1, const float* __restrict__ v1,
                          const float* __restrict__ g2, const float* __restrict__ b2,
                          const float* __restrict__ m2, const float* __restrict__ v2,
                          const float* __restrict__ W1, const float* __restrict__ Wd)
{
    int i = blockIdx.x * blockDim.x + threadIdx.x;
    if (i < DIM) {
        float s1 = g1[i] * rsqrtf(v1[i] + 1e-3f);
        g_s1[i] = s1; g_t1[i] = b1[i] - m1[i] * s1;
        float s2 = g2[i] * rsqrtf(v2[i] + 1e-3f);
        g_s2[i] = s2; g_t2[i] = b2[i] - m2[i] * s2;
    }
    if (i < DIM * DIM) {
        g_W1t[i] = wmma::__float_to_tf32(W1[i]);
        g_Wdt[i] = wmma::__float_to_tf32(Wd[i]);
    }
}

// ---------------- 2: rowptr (rows sorted; lower_bound per dest row) -------------
__global__ void build_rowptr(const int* __restrict__ rows, int n, int e)
{
    int r = blockIdx.x * blockDim.x + threadIdx.x;
    if (r > n) return;
    int lo = 0, hi = e;
    while (lo < hi) {
        int mid = (lo + hi) >> 1;
        if (rows[mid] < r) lo = mid + 1; else hi = mid;
    }
    g_rowptr[r] = lo;
}

// ---------------- 3: per-edge relation weights ev = adj/(relc[rel]+1) -----------
__global__ void edge_ev(const float* __restrict__ vals, const int* __restrict__ rel,
                        const float* __restrict__ relc, int e)
{
    int i = blockIdx.x * blockDim.x + threadIdx.x;
    if (i >= e) return;
    g_ev[i] = vals[i] / (relc[rel[i]] + 1.f);
}

// ----- shared GEMM core: cp.async W (pre-tf32) + register-path A (BN+cvt) -------
// Returns with sA holding the 64x128 fp32 result (post-MMA), all threads synced.
__device__ __forceinline__ void gemm_core(
    float* sW, float* sA,
    const float* __restrict__ A, const float* __restrict__ Wt,
    const float* __restrict__ bn_s, const float* __restrict__ bn_t,
    int r0, int n, int tid)
{
    // W tile via cp.async: no register round-trip, no conversion (pre-rounded)
    uint32_t swb = (uint32_t)__cvta_generic_to_shared(sW);
    const float4* W4 = (const float4*)Wt;
    #pragma unroll
    for (int k = 0; k < 16; k++) {
        int idx = tid + k * 256;          // float4 index over 128x128
        int row = idx >> 5, c4 = idx & 31;
        cp_async16(swb + (row * LDS_PAD + c4 * 4) * 4, &W4[idx]);
    }
    cp_async_commit();

    // A tile through registers (BN fold + tf32 round), overlapped with W in flight
    #pragma unroll
    for (int k = 0; k < 8; k++) {
        int idx = tid + k * 256;
        int row = idx >> 5, c4 = idx & 31;
        int gr = r0 + row;
        float4 a = make_float4(0.f, 0.f, 0.f, 0.f);
        if (gr < n) {
            a = ((const float4*)A)[gr * 32 + c4];
            if (bn_s) {
                int d = c4 * 4;
                a.x = a.x * bn_s[d + 0] + bn_t[d + 0];
                a.y = a.y * bn_s[d + 1] + bn_t[d + 1];
                a.z = a.z * bn_s[d + 2] + bn_t[d + 2];
                a.w = a.w * bn_s[d + 3] + bn_t[d + 3];
            }
            a.x = wmma::__float_to_tf32(a.x);
            a.y = wmma::__float_to_tf32(a.y);
            a.z = wmma::__float_to_tf32(a.z);
            a.w = wmma::__float_to_tf32(a.w);
        }
        *(float4*)&sA[row * LDS_PAD + c4 * 4] = a;
    }
    cp_async_wait_all();
    __syncthreads();

    const int wid = tid >> 5;
    const int wr  = wid >> 1;            // 0..3 : 16-row group
    const int wc  = wid & 1;             // 0..1 : 64-col group

    wmma::fragment<wmma::accumulator, 16, 16, 8, float> acc[4];
    #pragma unroll
    for (int j = 0; j < 4; j++) wmma::fill_fragment(acc[j], 0.f);

    #pragma unroll
    for (int kk = 0; kk < DIM; kk += 8) {
        wmma::fragment<wmma::matrix_a, 16, 16, 8, wmma::precision::tf32, wmma::row_major> af;
        wmma::load_matrix_sync(af, &sA[(wr * 16) * LDS_PAD + kk], LDS_PAD);
        #pragma unroll
        for (int j = 0; j < 4; j++) {
            wmma::fragment<wmma::matrix_b, 16, 16, 8, wmma::precision::tf32, wmma::row_major> bf;
            wmma::load_matrix_sync(bf, &sW[kk * LDS_PAD + wc * 64 + j * 16], LDS_PAD);
            wmma::mma_sync(acc[j], af, bf, acc[j]);
        }
    }

    __syncthreads();   // everyone done reading sA
    #pragma unroll
    for (int j = 0; j < 4; j++)
        wmma::store_matrix_sync(&sA[(wr * 16) * LDS_PAD + wc * 64 + j * 16],
                                acc[j], LDS_PAD, wmma::mem_row_major);
    __syncthreads();
}

// ---------------- 4: hW = BN1(x) @ W1t ------------------------------------------
__global__ void __launch_bounds__(256, 2)
gemm128_tf32(const float* __restrict__ A, const float* __restrict__ Wt,
             float* __restrict__ C,
             const float* __restrict__ bn_s, const float* __restrict__ bn_t, int n)
{
    extern __shared__ float sh[];
    float* sW = sh;
    float* sA = sh + DIM * LDS_PAD;
    const int tid = threadIdx.x;
    const int r0  = blockIdx.x * TM;

    gemm_core(sW, sA, A, Wt, bn_s, bn_t, r0, n, tid);

    #pragma unroll
    for (int k = 0; k < 8; k++) {
        int idx = tid + k * 256;          // 2048 float4 over 64x128
        int row = idx >> 5, c4 = idx & 31;
        int gr = r0 + row;
        if (gr >= n) continue;
        ((float4*)C)[gr * 32 + c4] = *(float4*)&sA[row * LDS_PAD + c4 * 4];
    }
}

// --------- 7: gemm2 (z @ Wdt + bd) FUSED with final l2-normalize-concat ---------
__global__ void __launch_bounds__(256, 2)
gemm128_norm(const float* __restrict__ A, const float* __restrict__ Wt,
             const float* __restrict__ bias,
             const float* __restrict__ x, const float* __restrict__ y1,
             float* __restrict__ out, int n)
{
    extern __shared__ float sh[];
    float* sW = sh;
    float* sA = sh + DIM * LDS_PAD;
    const int tid = threadIdx.x;
    const int r0  = blockIdx.x * TM;

    gemm_core(sW, sA, A, Wt, nullptr, nullptr, r0, n, tid);

    // epilogue: warp wid handles rows wid*8 .. wid*8+7; lane = col-group of 4
    const int wid = tid >> 5;
    const int lane = tid & 31;
    float4 bv = ((const float4*)bias)[lane];
    #pragma unroll
    for (int rr = 0; rr < 8; rr++) {
        int row = wid * 8 + rr;
        int gr  = r0 + row;
        if (gr >= n) continue;
        float4 c = *(float4*)&sA[row * LDS_PAD + lane * 4];
        c.x += bv.x; c.y += bv.y; c.z += bv.z; c.w += bv.w;
        float4 a = ((const float4*)x )[gr * 32 + lane];
        float4 b = ((const float4*)y1)[gr * 32 + lane];
        float sa = a.x*a.x + a.y*a.y + a.z*a.z + a.w*a.w;
        float sb = b.x*b.x + b.y*b.y + b.z*b.z + b.w*b.w;
        float sc = c.x*c.x + c.y*c.y + c.z*c.z + c.w*c.w;
        #pragma unroll
        for (int o = 16; o; o >>= 1) {
            sa += __shfl_xor_sync(0xffffffffu, sa, o);
            sb += __shfl_xor_sync(0xffffffffu, sb, o);
            sc += __shfl_xor_sync(0xffffffffu, sc, o);
        }
        float ra = rsqrtf(fmaxf(sa, 1e-12f));
        float rb = rsqrtf(fmaxf(sb, 1e-12f));
        float rc = rsqrtf(fmaxf(sc, 1e-12f));
        float na = sa * ra * ra, nb = sb * rb * rb, nc = sc * rc * rc;
        float rt = rsqrtf(fmaxf(na + nb + nc, 1e-12f));
        float fa = ra * rt, fb = rb * rt, fc = rc * rt;
        float4* O = (float4*)out;
        int obase = gr * 96;
        O[obase + lane]      = make_float4(a.x*fa, a.y*fa, a.z*fa, a.w*fa);
        O[obase + 32 + lane] = make_float4(b.x*fb, b.y*fb, b.z*fb, b.w*fb);
        O[obase + 64 + lane] = make_float4(c.x*fc, c.y*fc, c.z*fc, c.w*fc);
    }
}

// ---------------- 5: y1 = tanh(A @ hW + b1): warp/row, 4-deep gather pipeline ---
__global__ void spmm_tanh(const float* __restrict__ hW, const int* __restrict__ cols,
                          const float* __restrict__ vals, const float* __restrict__ b1,
                          float* __restrict__ y1, int n)
{
    int w = (blockIdx.x * blockDim.x + threadIdx.x) >> 5;
    int lane = threadIdx.x & 31;
    if (w >= n) return;
    int s = g_rowptr[w], e = g_rowptr[w + 1];
    const float4* H = (const float4*)hW;
    float4 acc = make_float4(0.f, 0.f, 0.f, 0.f);
    for (int base = s; base < e; base += 32) {
        int idx = base + lane;
        int   cl = 0; float vl = 0.f;
        if (idx < e) { cl = __ldg(&cols[idx]); vl = __ldg(&vals[idx]); }
        int m = min(32, e - base);
        int j = 0;
        for (; j + 4 <= m; j += 4) {
            int   c0 = __shfl_sync(0xffffffffu, cl, j);
            int   c1 = __shfl_sync(0xffffffffu, cl, j + 1);
            int   c2 = __shfl_sync(0xffffffffu, cl, j + 2);
            int   c3 = __shfl_sync(0xffffffffu, cl, j + 3);
            float v0 = __shfl_sync(0xffffffffu, vl, j);
            float v1 = __shfl_sync(0xffffffffu, vl, j + 1);
            float v2 = __shfl_sync(0xffffffffu, vl, j + 2);
            float v3 = __shfl_sync(0xffffffffu, vl, j + 3);
            float4 h0 = H[c0 * 32 + lane];
            float4 h1 = H[c1 * 32 + lane];
            float4 h2 = H[c2 * 32 + lane];
            float4 h3 = H[c3 * 32 + lane];
            acc.x += v0 * h0.x + v1 * h1.x + v2 * h2.x + v3 * h3.x;
            acc.y += v0 * h0.y + v1 * h1.y + v2 * h2.y + v3 * h3.y;
            acc.z += v0 * h0.z + v1 * h1.z + v2 * h2.z + v3 * h3.z;
            acc.w += v0 * h0.w + v1 * h1.w + v2 * h2.w + v3 * h3.w;
        }
        for (; j < m; j++) {
            int   c = __shfl_sync(0xffffffffu, cl, j);
            float v = __shfl_sync(0xffffffffu, vl, j);
            float4 h = H[c * 32 + lane];
            acc.x += v * h.x; acc.y += v * h.y; acc.z += v * h.z; acc.w += v * h.w;
        }
    }
    float4 b = ((const float4*)b1)[lane];
    float4 o = make_float4(tanhf(acc.x + b.x), tanhf(acc.y + b.y),
                           tanhf(acc.z + b.z), tanhf(acc.w + b.w));
    ((float4*)y1)[w * 32 + lane] = o;
}

// ---------------- 6: z = A_rel @ BN2(y1) + BN2(y1)*(ck+1)  (ev precomputed) -----
__global__ void spmm_rgin(const float* __restrict__ y1, const int* __restrict__ cols,
                          const float* __restrict__ ev, const float* __restrict__ ck,
                          float* __restrict__ z, int n)
{
    int w = (blockIdx.x * blockDim.x + threadIdx.x) >> 5;
    int lane = threadIdx.x & 31;
    if (w >= n) return;
    int s = g_rowptr[w], e = g_rowptr[w + 1];
    const float4* Y = (const float4*)y1;
    float4 accA = make_float4(0.f, 0.f, 0.f, 0.f);
    float  accB = 0.f;
    for (int base = s; base < e; base += 32) {
        int idx = base + lane;
        int cl = 0; float el = 0.f;
        if (idx < e) { cl = __ldg(&cols[idx]); el = __ldg(&ev[idx]); }
        int m = min(32, e - base);
        int j = 0;
        for (; j + 4 <= m; j += 4) {
            int   c0 = __shfl_sync(0xffffffffu, cl, j);
            int   c1 = __shfl_sync(0xffffffffu, cl, j + 1);
            int   c2 = __shfl_sync(0xffffffffu, cl, j + 2);
            int   c3 = __shfl_sync(0xffffffffu, cl, j + 3);
            float e0 = __shfl_sync(0xffffffffu, el, j);
            float e1 = __shfl_sync(0xffffffffu, el, j + 1);
            float e2 = __shfl_sync(0xffffffffu, el, j + 2);
            float e3 = __shfl_sync(0xffffffffu, el, j + 3);
            float4 h0 = Y[c0 * 32 + lane];
            float4 h1 = Y[c1 * 32 + lane];
            float4 h2 = Y[c2 * 32 + lane];
            float4 h3 = Y[c3 * 32 + lane];
            accA.x += e0 * h0.x + e1 * h1.x + e2 * h2.x + e3 * h3.x;
            accA.y += e0 * h0.y + e1 * h1.y + e2 * h2.y + e3 * h3.y;
            accA.z += e0 * h0.z + e1 * h1.z + e2 * h2.z + e3 * h3.z;
            accA.w += e0 * h0.w + e1 * h1.w + e2 * h2.w + e3 * h3.w;
            accB += e0 + e1 + e2 + e3;
        }
        for (; j < m; j++) {
            int   c  = __shfl_sync(0xffffffffu, cl, j);
            float ee = __shfl_sync(0xffffffffu, el, j);
            float4 h = Y[c * 32 + lane];
            accA.x += ee * h.x; accA.y += ee * h.y;
            accA.z += ee * h.z; accA.w += ee * h.w;
            accB += ee;
        }
    }
    int d = lane * 4;
    float4 s2 = *(const float4*)&g_s2[d];
    float4 t2 = *(const float4*)&g_t2[d];
    float4 yr = Y[w * 32 + lane];
    float  cm = __ldg(&ck[w]) + 1.f;
    float4 o;
    o.x = s2.x * accA.x + t2.x * accB + (yr.x * s2.x + t2.x) * cm;
    o.y = s2.y * accA.y + t2.y * accB + (yr.y * s2.y + t2.y) * cm;
    o.z = s2.z * accA.z + t2.z * accB + (yr.z * s2.z + t2.z) * cm;
    o.w = s2.w * accA.w + t2.w * accB + (yr.w * s2.w + t2.w) * cm;
    ((float4*)z)[w * 32 + lane] = o;
}

// ---------------- launch --------------------------------------------------------
extern "C" void kernel_launch(void* const* d_in, const int* in_sizes, int n_in,
                              void* d_out, int out_size)
{
    const float* x      = (const float*)d_in[0];
    const int*   rows   = (const int*)  d_in[1];
    const int*   cols   = (const int*)  d_in[2];
    const float* adj    = (const float*)d_in[3];
    const int*   rel    = (const int*)  d_in[4];
    const float* gamma1 = (const float*)d_in[5];
    const float* beta1  = (const float*)d_in[6];
    const float* mean1  = (const float*)d_in[7];
    const float* var1   = (const float*)d_in[8];
    const float* W1     = (const float*)d_in[9];
    const float* b1     = (const float*)d_in[10];
    const float* gamma2 = (const float*)d_in[11];
    const float* beta2  = (const float*)d_in[12];
    const float* mean2  = (const float*)d_in[13];
    const float* var2   = (const float*)d_in[14];
    const float* relc   = (const float*)d_in[15];
    const float* ck     = (const float*)d_in[16];
    const float* Wd     = (const float*)d_in[17];
    const float* bd     = (const float*)d_in[18];
    float* out = (float*)d_out;

    const int n = in_sizes[0] / DIM;     // 50000
    const int e = in_sizes[1];           // 640000

    cudaFuncSetAttribute(gemm128_tf32, cudaFuncAttributeMaxDynamicSharedMemorySize, GEMM_SMEM);
    cudaFuncSetAttribute(gemm128_norm, cudaFuncAttributeMaxDynamicSharedMemorySize, GEMM_SMEM);

    // __device__ symbols are NOT valid host-side pointers — fetch device addresses.
    float *hW, *y1, *z, *ev, *s1, *t1, *W1t, *Wdt;
    cudaGetSymbolAddress((void**)&hW,  g_hW);
    cudaGetSymbolAddress((void**)&y1,  g_y1);
    cudaGetSymbolAddress((void**)&z,   g_z);
    cudaGetSymbolAddress((void**)&ev,  g_ev);
    cudaGetSymbolAddress((void**)&s1,  g_s1);
    cudaGetSymbolAddress((void**)&t1,  g_t1);
    cudaGetSymbolAddress((void**)&W1t, g_W1t);
    cudaGetSymbolAddress((void**)&Wdt, g_Wdt);

    prep_bn_w<<<(DIM*DIM + 255) / 256, 256>>>(gamma1, beta1, mean1, var1,
                                              gamma2, beta2, mean2, var2, W1, Wd);
    build_rowptr<<<(n + 1 + 255) / 256, 256>>>(rows, n, e);
    edge_ev<<<(e + 255) / 256, 256>>>(adj, rel, relc, e);

    int gemm_blocks = (n + TM - 1) / TM;
    gemm128_tf32<<<gemm_blocks, 256, GEMM_SMEM>>>(x, W1t, hW, s1, t1, n);

    int warp_blocks = (n * 32 + 255) / 256;
    spmm_tanh<<<warp_blocks, 256>>>(hW, cols, adj, b1, y1, n);
    spmm_rgin<<<warp_blocks, 256>>>(y1, cols, ev, ck, z, n);

    gemm128_norm<<<gemm_blocks, 256, GEMM_SMEM>>>(z, Wdt, bd, x, y1, out, n);
}

// round 11
// speedup vs baseline: 1.4046x; 1.2406x over previous
#include <cuda_runtime.h>
#include <mma.h>
#include <math.h>
#include <cstdint>

using namespace nvcuda;

// Problem constants (fixed by the dataset)
#define N_NODES 50000
#define DIM     128
#define N_EDGES 640000

// GEMM: block = 256 thr (8 warps), tile 64 rows x 128 cols, raw mma.m16n8k8.tf32
#define TM 64
#define SW_FLOATS 16384                   // W fragment-ordered: [16 nf][16 kk][32 lane][2]
#define SA_STRIDE 132                     // kk-stride in floats (128 + 4 pad, kills STS conflicts)
#define SA_FLOATS (64 * SA_STRIDE)        // [4 mg][16 kk] x 132  == also 64x132 stage buffer
#define GEMM_SMEM ((SW_FLOATS + SA_FLOATS) * 4)   // 65536 + 33792 = 99328 B -> 2 blocks/SM

// ---------------- scratch (device globals; no allocation allowed) ----------------
__device__ float g_hW[N_NODES*DIM];
__device__ float g_y1[N_NODES*DIM];
__device__ float g_z [N_NODES*DIM];
__device__ float g_ev[N_EDGES];
__device__ float g_Wp1[SW_FLOATS];        // W1 (BN1-folded, tf32) in B-fragment order
__device__ float g_Wpd[SW_FLOATS];        // Wd (tf32) in B-fragment order
__device__ float g_b1p[DIM];              // bias from BN1 shift: sum_k t1[k]*W1[k][n]
__device__ int   g_rowptr[N_NODES+1];
__device__ float g_s1[DIM], g_t1[DIM], g_s2[DIM], g_t2[DIM];

__device__ __forceinline__ void cp_async16(uint32_t smem_addr, const void* gptr) {
    asm volatile("cp.async.cg.shared.global [%0], [%1], 16;\n"
                 :: "r"(smem_addr), "l"(gptr) : "memory");
}
__device__ __forceinline__ void cp_async_commit() {
    asm volatile("cp.async.commit_group;\n" ::: "memory");
}
__device__ __forceinline__ void cp_async_wait_all() {
    asm volatile("cp.async.wait_group 0;\n" ::: "memory");
}

__device__ __forceinline__ void mma_tf32(float acc[4], const uint32_t a[4], const uint32_t b[2]) {
    asm volatile("mma.sync.aligned.m16n8k8.row.col.f32.tf32.tf32.f32 "
                 "{%0,%1,%2,%3}, {%4,%5,%6,%7}, {%8,%9}, {%0,%1,%2,%3};"
                 : "+f"(acc[0]), "+f"(acc[1]), "+f"(acc[2]), "+f"(acc[3])
                 : "r"(a[0]), "r"(a[1]), "r"(a[2]), "r"(a[3]), "r"(b[0]), "r"(b[1]));
}

// ---------------- 1: BN folding ------------------------------------------------
__global__ void prep_bn(const float* __restrict__ g1, const float* __restrict__ b1,
                        const float* __restrict__ m1, const float* __restrict__ v1,
                        const float* __restrict__ g2, const float* __restrict__ b2,
                        const float* __restrict__ m2, const float* __restrict__ v2)
{
    int d = threadIdx.x;
    float s1 = g1[d] * rsqrtf(v1[d] + 1e-3f);
    g_s1[d] = s1; g_t1[d] = b1[d] - m1[d] * s1;
    float s2 = g2[d] * rsqrtf(v2[d] + 1e-3f);
    g_s2[d] = s2; g_t2[d] = b2[d] - m2[d] * s2;
}

// ---------------- 2: W permute to mma B-fragment order + BN1 fold ---------------
// B frag (m16n8k8.row.col): b0 = W[k = kk*8 + lane%4    ][n = nf*8 + lane/4]
//                           b1 = W[k = kk*8 + lane%4 + 4][n = nf*8 + lane/4]
// flat index i = ((nf*16 + kk)*32 + lane)*2 + t
__global__ void prep_w(const float* __restrict__ W1, const float* __restrict__ Wd)
{
    int i = blockIdx.x * blockDim.x + threadIdx.x;
    if (i < SW_FLOATS) {
        int t    = i & 1;
        int lane = (i >> 1) & 31;
        int kk   = (i >> 6) & 15;
        int nf   = i >> 10;
        int k = kk * 8 + (lane & 3) + 4 * t;
        int nn = nf * 8 + (lane >> 2);
        g_Wp1[i] = wmma::__float_to_tf32(g_s1[k] * W1[k * DIM + nn]);
        g_Wpd[i] = wmma::__float_to_tf32(Wd[k * DIM + nn]);
    }
    // bias fold: b1p[n] = sum_k t1[k] * W1[k][n]   (block 0, threads 0..127)
    if (blockIdx.x == 0 && threadIdx.x < DIM) {
        int nn = threadIdx.x;
        float s = 0.f;
        for (int k = 0; k < DIM; k++) s += g_t1[k] * W1[k * DIM + nn];
        g_b1p[nn] = s;
    }
}

// ---------------- 3: rowptr (rows sorted; lower_bound per dest row) -------------
__global__ void build_rowptr(const int* __restrict__ rows, int n, int e)
{
    int r = blockIdx.x * blockDim.x + threadIdx.x;
    if (r > n) return;
    int lo = 0, hi = e;
    while (lo < hi) {
        int mid = (lo + hi) >> 1;
        if (rows[mid] < r) lo = mid + 1; else hi = mid;
    }
    g_rowptr[r] = lo;
}

// ---------------- 4: per-edge relation weights ev = adj/(relc[rel]+1) -----------
__global__ void edge_ev(const float* __restrict__ vals, const int* __restrict__ rel,
                        const float* __restrict__ relc, int e)
{
    int i = blockIdx.x * blockDim.x + threadIdx.x;
    if (i >= e) return;
    g_ev[i] = vals[i] / (relc[rel[i]] + 1.f);
}

// ----- GEMM core: fragment-ordered smem, raw mma; fills acc[8][4] ---------------
// A frag (m16n8k8.row): a0=(g,c) a1=(g+8,c) a2=(g,c+4) a3=(g+8,c+4); g=lane/4,c=lane%4
// sA layout: [(mg*16+kk)*132 + lane*4 + j]
__device__ __forceinline__ void gemm_mma_core(
    float* sW, float* sA,
    const float* __restrict__ A, const float* __restrict__ Wp,
    int r0, int n, int tid, float acc[8][4])
{
    uint32_t swb = (uint32_t)__cvta_generic_to_shared(sW);
    const float4* W4 = (const float4*)Wp;
    #pragma unroll
    for (int k = 0; k < 16; k++) {
        int idx = tid + k * 256;          // float4 idx over 16384 floats
        cp_async16(swb + idx * 16, W4 + idx);
    }
    cp_async_commit();

    // A tile -> tf32 -> fragment-ordered scatter (4 STS.32, conflict-light)
    #pragma unroll
    for (int k = 0; k < 8; k++) {
        int idx = tid + k * 256;
        int row = idx >> 5, q = idx & 31;
        int gr = r0 + row;
        float4 a = make_float4(0.f, 0.f, 0.f, 0.f);
        if (gr < n) a = ((const float4*)A)[gr * 32 + q];
        a.x = wmma::__float_to_tf32(a.x);
        a.y = wmma::__float_to_tf32(a.y);
        a.z = wmma::__float_to_tf32(a.z);
        a.w = wmma::__float_to_tf32(a.w);
        int mg = row >> 4, g = row & 7, jr = (row >> 3) & 1;
        int kk = q >> 1, j = (q & 1) * 2 + jr;
        float* dst = &sA[(mg * 16 + kk) * SA_STRIDE + j];
        dst[(g * 4 + 0) * 4] = a.x;
        dst[(g * 4 + 1) * 4] = a.y;
        dst[(g * 4 + 2) * 4] = a.z;
        dst[(g * 4 + 3) * 4] = a.w;
    }
    cp_async_wait_all();
    __syncthreads();

    const int wid = tid >> 5, lane = tid & 31;
    const int mg = wid >> 1, nh = wid & 1;
    #pragma unroll
    for (int nf = 0; nf < 8; nf++)
        acc[nf][0] = acc[nf][1] = acc[nf][2] = acc[nf][3] = 0.f;

    #pragma unroll
    for (int kk = 0; kk < 16; kk++) {
        uint32_t au[4];
        float4 av = *(const float4*)&sA[(mg * 16 + kk) * SA_STRIDE + lane * 4];
        au[0] = __float_as_uint(av.x); au[1] = __float_as_uint(av.y);
        au[2] = __float_as_uint(av.z); au[3] = __float_as_uint(av.w);
        #pragma unroll
        for (int nf = 0; nf < 8; nf++) {
            uint32_t bu[2];
            float2 bv = *(const float2*)&sW[((nh * 8 + nf) * 16 + kk) * 64 + lane * 2];
            bu[0] = __float_as_uint(bv.x); bu[1] = __float_as_uint(bv.y);
            mma_tf32(acc[nf], au, bu);
        }
    }
    __syncthreads();   // sA free for reuse by caller
}

// ---------------- 5: hW = x @ W1' + b1p  (BN1 folded into W1') ------------------
__global__ void __launch_bounds__(256, 2)
gemm128_a(const float* __restrict__ A, const float* __restrict__ Wp,
          const float* __restrict__ bias, float* __restrict__ C, int n)
{
    extern __shared__ float sh[];
    float* sW = sh;
    float* sA = sh + SW_FLOATS;
    const int tid = threadIdx.x;
    const int r0  = blockIdx.x * TM;

    float acc[8][4];
    gemm_mma_core(sW, sA, A, Wp, r0, n, tid, acc);

    // direct store from accumulators (c0,c1 rows g; c2,c3 rows g+8; cols 2c,2c+1)
    const int wid = tid >> 5, lane = tid & 31;
    const int mg = wid >> 1, nh = wid & 1;
    const int g = lane >> 2, c = lane & 3;
    int r_lo = r0 + mg * 16 + g;
    #pragma unroll
    for (int nf = 0; nf < 8; nf++) {
        int col = nh * 64 + nf * 8 + c * 2;
        float2 bp = *(const float2*)&bias[col];
        if (r_lo < n)
            *(float2*)&C[r_lo * DIM + col] =
                make_float2(acc[nf][0] + bp.x, acc[nf][1] + bp.y);
        if (r_lo + 8 < n)
            *(float2*)&C[(r_lo + 8) * DIM + col] =
                make_float2(acc[nf][2] + bp.x, acc[nf][3] + bp.y);
    }
}

// -------- 8: gemm2 (z @ Wd' + bd) FUSED with final l2-normalize-concat ----------
__global__ void __launch_bounds__(256, 2)
gemm128_norm(const float* __restrict__ A, const float* __restrict__ Wp,
             const float* __restrict__ bias,
             const float* __restrict__ x, const float* __restrict__ y1,
             float* __restrict__ out, int n)
{
    extern __shared__ float sh[];
    float* sW = sh;
    float* sA = sh + SW_FLOATS;
    const int tid = threadIdx.x;
    const int r0  = blockIdx.x * TM;

    float acc[8][4];
    gemm_mma_core(sW, sA, A, Wp, r0, n, tid, acc);

    // stage result rows into sA (64 x 128, stride 132)
    const int wid = tid >> 5, lane = tid & 31;
    const int mg = wid >> 1, nh = wid & 1;
    const int g = lane >> 2, c = lane & 3;
    #pragma unroll
    for (int nf = 0; nf < 8; nf++) {
        int col = nh * 64 + nf * 8 + c * 2;
        int lr = mg * 16 + g;
        *(float2*)&sA[lr * SA_STRIDE + col]       = make_float2(acc[nf][0], acc[nf][1]);
        *(float2*)&sA[(lr + 8) * SA_STRIDE + col] = make_float2(acc[nf][2], acc[nf][3]);
    }
    __syncthreads();

    // per-warp norm epilogue: warp wid handles rows wid*8 .. wid*8+7
    float4 bv = ((const float4*)bias)[lane];
    #pragma unroll
    for (int rr = 0; rr < 8; rr++) {
        int row = wid * 8 + rr;
        int gr  = r0 + row;
        if (gr >= n) continue;
        float4 cc = *(float4*)&sA[row * SA_STRIDE + lane * 4];
        cc.x += bv.x; cc.y += bv.y; cc.z += bv.z; cc.w += bv.w;
        float4 a = ((const float4*)x )[gr * 32 + lane];
        float4 b = ((const float4*)y1)[gr * 32 + lane];
        float sa = a.x*a.x + a.y*a.y + a.z*a.z + a.w*a.w;
        float sb = b.x*b.x + b.y*b.y + b.z*b.z + b.w*b.w;
        float sc = cc.x*cc.x + cc.y*cc.y + cc.z*cc.z + cc.w*cc.w;
        #pragma unroll
        for (int o = 16; o; o >>= 1) {
            sa += __shfl_xor_sync(0xffffffffu, sa, o);
            sb += __shfl_xor_sync(0xffffffffu, sb, o);
            sc += __shfl_xor_sync(0xffffffffu, sc, o);
        }
        float ra = rsqrtf(fmaxf(sa, 1e-12f));
        float rb = rsqrtf(fmaxf(sb, 1e-12f));
        float rc = rsqrtf(fmaxf(sc, 1e-12f));
        float na = sa * ra * ra, nb = sb * rb * rb, nc = sc * rc * rc;
        float rt = rsqrtf(fmaxf(na + nb + nc, 1e-12f));
        float fa = ra * rt, fb = rb * rt, fc = rc * rt;
        float4* O = (float4*)out;
        int obase = gr * 96;
        O[obase + lane]      = make_float4(a.x*fa, a.y*fa, a.z*fa, a.w*fa);
        O[obase + 32 + lane] = make_float4(b.x*fb, b.y*fb, b.z*fb, b.w*fb);
        O[obase + 64 + lane] = make_float4(cc.x*fc, cc.y*fc, cc.z*fc, cc.w*fc);
    }
}

// ---------------- 6: y1 = tanh(A @ hW + b1): warp/row, 4-deep gather pipeline ---
__global__ void spmm_tanh(const float* __restrict__ hW, const int* __restrict__ cols,
                          const float* __restrict__ vals, const float* __restrict__ b1,
                          float* __restrict__ y1, int n)
{
    int w = (blockIdx.x * blockDim.x + threadIdx.x) >> 5;
    int lane = threadIdx.x & 31;
    if (w >= n) return;
    int s = g_rowptr[w], e = g_rowptr[w + 1];
    const float4* H = (const float4*)hW;
    float4 acc = make_float4(0.f, 0.f, 0.f, 0.f);
    for (int base = s; base < e; base += 32) {
        int idx = base + lane;
        int   cl = 0; float vl = 0.f;
        if (idx < e) { cl = __ldg(&cols[idx]); vl = __ldg(&vals[idx]); }
        int m = min(32, e - base);
        int j = 0;
        for (; j + 4 <= m; j += 4) {
            int   c0 = __shfl_sync(0xffffffffu, cl, j);
            int   c1 = __shfl_sync(0xffffffffu, cl, j + 1);
            int   c2 = __shfl_sync(0xffffffffu, cl, j + 2);
            int   c3 = __shfl_sync(0xffffffffu, cl, j + 3);
            float v0 = __shfl_sync(0xffffffffu, vl, j);
            float v1 = __shfl_sync(0xffffffffu, vl, j + 1);
            float v2 = __shfl_sync(0xffffffffu, vl, j + 2);
            float v3 = __shfl_sync(0xffffffffu, vl, j + 3);
            float4 h0 = H[c0 * 32 + lane];
            float4 h1 = H[c1 * 32 + lane];
            float4 h2 = H[c2 * 32 + lane];
            float4 h3 = H[c3 * 32 + lane];
            acc.x += v0 * h0.x + v1 * h1.x + v2 * h2.x + v3 * h3.x;
            acc.y += v0 * h0.y + v1 * h1.y + v2 * h2.y + v3 * h3.y;
            acc.z += v0 * h0.z + v1 * h1.z + v2 * h2.z + v3 * h3.z;
            acc.w += v0 * h0.w + v1 * h1.w + v2 * h2.w + v3 * h3.w;
        }
        for (; j < m; j++) {
            int   c = __shfl_sync(0xffffffffu, cl, j);
            float v = __shfl_sync(0xffffffffu, vl, j);
            float4 h = H[c * 32 + lane];
            acc.x += v * h.x; acc.y += v * h.y; acc.z += v * h.z; acc.w += v * h.w;
        }
    }
    float4 b = ((const float4*)b1)[lane];
    float4 o = make_float4(tanhf(acc.x + b.x), tanhf(acc.y + b.y),
                           tanhf(acc.z + b.z), tanhf(acc.w + b.w));
    ((float4*)y1)[w * 32 + lane] = o;
}

// ---------------- 7: z = A_rel @ BN2(y1) + BN2(y1)*(ck+1)  (ev precomputed) -----
__global__ void spmm_rgin(const float* __restrict__ y1, const int* __restrict__ cols,
                          const float* __restrict__ ev, const float* __restrict__ ck,
                          float* __restrict__ z, int n)
{
    int w = (blockIdx.x * blockDim.x + threadIdx.x) >> 5;
    int lane = threadIdx.x & 31;
    if (w >= n) return;
    int s = g_rowptr[w], e = g_rowptr[w + 1];
    const float4* Y = (const float4*)y1;
    float4 accA = make_float4(0.f, 0.f, 0.f, 0.f);
    float  accB = 0.f;
    for (int base = s; base < e; base += 32) {
        int idx = base + lane;
        int cl = 0; float el = 0.f;
        if (idx < e) { cl = __ldg(&cols[idx]); el = __ldg(&ev[idx]); }
        int m = min(32, e - base);
        int j = 0;
        for (; j + 4 <= m; j += 4) {
            int   c0 = __shfl_sync(0xffffffffu, cl, j);
            int   c1 = __shfl_sync(0xffffffffu, cl, j + 1);
            int   c2 = __shfl_sync(0xffffffffu, cl, j + 2);
            int   c3 = __shfl_sync(0xffffffffu, cl, j + 3);
            float e0 = __shfl_sync(0xffffffffu, el, j);
            float e1 = __shfl_sync(0xffffffffu, el, j + 1);
            float e2 = __shfl_sync(0xffffffffu, el, j + 2);
            float e3 = __shfl_sync(0xffffffffu, el, j + 3);
            float4 h0 = Y[c0 * 32 + lane];
            float4 h1 = Y[c1 * 32 + lane];
            float4 h2 = Y[c2 * 32 + lane];
            float4 h3 = Y[c3 * 32 + lane];
            accA.x += e0 * h0.x + e1 * h1.x + e2 * h2.x + e3 * h3.x;
            accA.y += e0 * h0.y + e1 * h1.y + e2 * h2.y + e3 * h3.y;
            accA.z += e0 * h0.z + e1 * h1.z + e2 * h2.z + e3 * h3.z;
            accA.w += e0 * h0.w + e1 * h1.w + e2 * h2.w + e3 * h3.w;
            accB += e0 + e1 + e2 + e3;
        }
        for (; j < m; j++) {
            int   c  = __shfl_sync(0xffffffffu, cl, j);
            float ee = __shfl_sync(0xffffffffu, el, j);
            float4 h = Y[c * 32 + lane];
            accA.x += ee * h.x; accA.y += ee * h.y;
            accA.z += ee * h.z; accA.w += ee * h.w;
            accB += ee;
        }
    }
    int d = lane * 4;
    float4 s2 = *(const float4*)&g_s2[d];
    float4 t2 = *(const float4*)&g_t2[d];
    float4 yr = Y[w * 32 + lane];
    float  cm = __ldg(&ck[w]) + 1.f;
    float4 o;
    o.x = s2.x * accA.x + t2.x * accB + (yr.x * s2.x + t2.x) * cm;
    o.y = s2.y * accA.y + t2.y * accB + (yr.y * s2.y + t2.y) * cm;
    o.z = s2.z * accA.z + t2.z * accB + (yr.z * s2.z + t2.z) * cm;
    o.w = s2.w * accA.w + t2.w * accB + (yr.w * s2.w + t2.w) * cm;
    ((float4*)z)[w * 32 + lane] = o;
}

// ---------------- launch --------------------------------------------------------
extern "C" void kernel_launch(void* const* d_in, const int* in_sizes, int n_in,
                              void* d_out, int out_size)
{
    const float* x      = (const float*)d_in[0];
    const int*   rows   = (const int*)  d_in[1];
    const int*   cols   = (const int*)  d_in[2];
    const float* adj    = (const float*)d_in[3];
    const int*   rel    = (const int*)  d_in[4];
    const float* gamma1 = (const float*)d_in[5];
    const float* beta1  = (const float*)d_in[6];
    const float* mean1  = (const float*)d_in[7];
    const float* var1   = (const float*)d_in[8];
    const float* W1     = (const float*)d_in[9];
    const float* b1     = (const float*)d_in[10];
    const float* gamma2 = (const float*)d_in[11];
    const float* beta2  = (const float*)d_in[12];
    const float* mean2  = (const float*)d_in[13];
    const float* var2   = (const float*)d_in[14];
    const float* relc   = (const float*)d_in[15];
    const float* ck     = (const float*)d_in[16];
    const float* Wd     = (const float*)d_in[17];
    const float* bd     = (const float*)d_in[18];
    float* out = (float*)d_out;

    const int n = in_sizes[0] / DIM;     // 50000
    const int e = in_sizes[1];           // 640000

    cudaFuncSetAttribute(gemm128_a,    cudaFuncAttributeMaxDynamicSharedMemorySize, GEMM_SMEM);
    cudaFuncSetAttribute(gemm128_norm, cudaFuncAttributeMaxDynamicSharedMemorySize, GEMM_SMEM);

    // __device__ symbols are NOT valid host-side pointers — fetch device addresses.
    float *hW, *y1, *z, *ev, *Wp1, *Wpd, *b1p;
    cudaGetSymbolAddress((void**)&hW,  g_hW);
    cudaGetSymbolAddress((void**)&y1,  g_y1);
    cudaGetSymbolAddress((void**)&z,   g_z);
    cudaGetSymbolAddress((void**)&ev,  g_ev);
    cudaGetSymbolAddress((void**)&Wp1, g_Wp1);
    cudaGetSymbolAddress((void**)&Wpd, g_Wpd);
    cudaGetSymbolAddress((void**)&b1p, g_b1p);

    prep_bn<<<1, DIM>>>(gamma1, beta1, mean1, var1, gamma2, beta2, mean2, var2);
    prep_w<<<(SW_FLOATS + 255) / 256, 256>>>(W1, Wd);
    build_rowptr<<<(n + 1 + 255) / 256, 256>>>(rows, n, e);
    edge_ev<<<(e + 255) / 256, 256>>>(adj, rel, relc, e);

    int gemm_blocks = (n + TM - 1) / TM;
    gemm128_a<<<gemm_blocks, 256, GEMM_SMEM>>>(x, Wp1, b1p, hW, n);

    int warp_blocks = (n * 32 + 255) / 256;
    spmm_tanh<<<warp_blocks, 256>>>(hW, cols, adj, b1, y1, n);
    spmm_rgin<<<warp_blocks, 256>>>(y1, cols, ev, ck, z, n);

    gemm128_norm<<<gemm_blocks, 256, GEMM_SMEM>>>(z, Wpd, bd, x, y1, out, n);
}